// round 14
// baseline (speedup 1.0000x reference)
#include <cuda_runtime.h>
#include <cuda_fp16.h>
#include <mma.h>
#include <math.h>

#define NN 50000
#define NE 800000
#define D 128
#define ROWS 64           // rows per CTA tile
#define PA 136            // padded panel row (fp16 elems), 272B rows
#define PAB (PA * 2)
#define NBLK 196          // scan blocks: ceil(NN/256)

// smem byte offsets (per-CTA total 70656)
#define XA_HI 0           // 64 x 136 fp16 = 17408
#define H_HI  17408
#define BUF0  34816       // three 8704B B quarter-buffers (rotation)
#define SCR   34816       // f32 scratch 64x132 (33792B) overlays buffers
#define SB    68608       // 512 f32 biases
#define SM_TOTAL (68608 + 2048)

typedef unsigned int u32;
using namespace nvcuda;
typedef wmma::fragment<wmma::matrix_a, 16, 16, 16, __half, wmma::row_major> FragA;
typedef wmma::fragment<wmma::matrix_b, 16, 16, 16, __half, wmma::row_major> FragB;
typedef wmma::fragment<wmma::accumulator, 16, 16, 16, float> FragC;

// ---------------- scratch (device globals; no allocation allowed) ----------
__device__ int   g_cnt[NN];         // in-degree counts (excl self-loop)
__device__ int   g_part[NBLK];      // scan block partials
__device__ float g_dinv[NN];
__device__ __half g_xs[NN * D];     // fp16 pre-scaled features; z-scratch in k_main
__device__ float g_agg[NN * D];     // f32 aggregate (written by k_agg)
__device__ int   g_rowptr[NN + 1];
__device__ int   g_cur[NN];
__device__ int   g_elist[NE];
__device__ float g_Wf[3 * D * D];
__device__ float g_bf[3 * D];
__device__ __half g_B[7 * 16384];   // 7 B mats [k][n] fp16

__device__ __forceinline__ u32 s2u(const void* p) {
    u32 a;
    asm("{ .reg .u64 t; cvta.to.shared.u64 t, %1; cvt.u32.u64 %0, t; }"
        : "=r"(a) : "l"(p));
    return a;
}
__device__ __forceinline__ float sigm(float x) { return 1.0f / (1.0f + expf(-x)); }
__device__ __forceinline__ u32 pk2h(float x0, float x1) {
    __half2 hh = __floats2half2_rn(x0, x1);
    return *(u32*)&hh;
}
__device__ __forceinline__ float2 up2h(u32 v) {
    return __half22float2(*(__half2*)&v);
}

// ---------------- graph prep kernels ----------------------------------------
__global__ void k_init() {
    int i = blockIdx.x * blockDim.x + threadIdx.x;
    if (i < NN) g_cnt[i] = 0;
}
__global__ void k_count(const int* __restrict__ dst) {
    int e = blockIdx.x * blockDim.x + threadIdx.x;
    if (e < NE) atomicAdd(&g_cnt[dst[e]], 1);
}
// xs = fp16(dinv * x); dinv
__global__ void k_prescale(const float* __restrict__ x) {
    int idx = blockIdx.x * blockDim.x + threadIdx.x;
    if (idx >= NN * 32) return;
    int i = idx >> 5, c = idx & 31;
    float dv = rsqrtf((float)(g_cnt[i] + 1));
    float4 v = ((const float4*)x)[idx];
    uint2 q;
    q.x = pk2h(dv * v.x, dv * v.y);
    q.y = pk2h(dv * v.z, dv * v.w);
    ((uint2*)g_xs)[idx] = q;
    if (c == 0) g_dinv[i] = dv;
}
// ---- 3-phase exclusive scan of g_cnt -> g_rowptr ----
__global__ void k_scanA() {
    __shared__ int sh[256];
    int t = threadIdx.x;
    int idx = blockIdx.x * 256 + t;
    int v = (idx < NN) ? g_cnt[idx] : 0;
    sh[t] = v;
    __syncthreads();
    #pragma unroll
    for (int o = 1; o < 256; o <<= 1) {
        int u = (t >= o) ? sh[t - o] : 0;
        __syncthreads();
        sh[t] += u;
        __syncthreads();
    }
    if (idx < NN) g_rowptr[idx] = sh[t] - v;     // block-local exclusive
    if (t == 255) g_part[blockIdx.x] = sh[255];  // block total
}
__global__ void k_scanB() {
    __shared__ int sh[NBLK];
    int t = threadIdx.x;
    int v = (t < NBLK) ? g_part[t] : 0;
    if (t < NBLK) sh[t] = v;
    __syncthreads();
    for (int o = 1; o < NBLK; o <<= 1) {
        int u = (t >= o && t < NBLK) ? sh[t - o] : 0;
        __syncthreads();
        if (t < NBLK) sh[t] += u;
        __syncthreads();
    }
    if (t < NBLK) g_part[t] = sh[t] - v;         // exclusive
}
__global__ void k_scanC() {
    int idx = blockIdx.x * 256 + threadIdx.x;
    if (idx < NN) {
        int r = g_rowptr[idx] + g_part[blockIdx.x];
        g_rowptr[idx] = r;
        g_cur[idx] = r;
    }
    if (idx == 0) g_rowptr[NN] = NE;
}
// scatter edges into dst-grouped list (scalar atomics on 50K cursors)
__global__ void k_scatter(const int* __restrict__ src, const int* __restrict__ dst) {
    int e = blockIdx.x * blockDim.x + threadIdx.x;
    if (e >= NE) return;
    int pos = atomicAdd(&g_cur[dst[e]], 1);
    g_elist[pos] = src[e];
}
// warp-per-node aggregation: agg[n] = dinv[n]*x[n] + sum_{src in list} xs[src]
__global__ void k_agg(const float* __restrict__ x) {
    int n = blockIdx.x * 8 + (threadIdx.x >> 5);
    if (n >= NN) return;
    int lane = threadIdx.x & 31;
    float dv = g_dinv[n];
    float4 self = ((const float4*)x)[n * 32 + lane];
    float a0 = dv * self.x, a1 = dv * self.y, a2 = dv * self.z, a3 = dv * self.w;
    int j = g_rowptr[n], fin = g_rowptr[n + 1];
    for (; j + 1 < fin; j += 2) {
        int s0 = __ldg(&g_elist[j]);
        int s1 = __ldg(&g_elist[j + 1]);
        uint2 q0 = ((const uint2*)g_xs)[s0 * 32 + lane];
        uint2 q1 = ((const uint2*)g_xs)[s1 * 32 + lane];
        float2 p0 = up2h(q0.x), p1 = up2h(q0.y);
        float2 p2 = up2h(q1.x), p3 = up2h(q1.y);
        a0 += p0.x + p2.x; a1 += p0.y + p2.y;
        a2 += p1.x + p3.x; a3 += p1.y + p3.y;
    }
    if (j < fin) {
        int s0 = __ldg(&g_elist[j]);
        uint2 q0 = ((const uint2*)g_xs)[s0 * 32 + lane];
        float2 p0 = up2h(q0.x), p1 = up2h(q0.y);
        a0 += p0.x; a1 += p0.y; a2 += p1.x; a3 += p1.y;
    }
    ((float4*)g_agg)[n * 32 + lane] = make_float4(a0, a1, a2, a3);
}

// ---------------- weight fusion + fp16 quantization --------------------------
__global__ void k_fuse(const float* __restrict__ Wc_z, const float* __restrict__ Wl_z,
                       const float* __restrict__ bc_z, const float* __restrict__ bl_z,
                       const float* __restrict__ Wc_r, const float* __restrict__ Wl_r,
                       const float* __restrict__ bc_r, const float* __restrict__ bl_r,
                       const float* __restrict__ Wc_h, const float* __restrict__ Wl_h,
                       const float* __restrict__ bc_h, const float* __restrict__ bl_h) {
    int g = blockIdx.y;
    const float* Wc = (g == 0) ? Wc_z : (g == 1) ? Wc_r : Wc_h;
    const float* Wl = (g == 0) ? Wl_z : (g == 1) ? Wl_r : Wl_h;
    const float* bc = (g == 0) ? bc_z : (g == 1) ? bc_r : bc_h;
    const float* bl = (g == 0) ? bl_z : (g == 1) ? bl_r : bl_h;
    int i = blockIdx.x;
    int j = threadIdx.x;
    float s = 0.0f;
    #pragma unroll 8
    for (int k = 0; k < D; ++k) s += Wc[i * D + k] * Wl[k * D + j];
    g_Wf[g * D * D + i * D + j] = s;
    if (i == 0) {
        float b = bl[j];
        #pragma unroll 8
        for (int k = 0; k < D; ++k) b += bc[k] * Wl[k * D + j];
        g_bf[g * D + j] = b;
    }
}

__global__ void k_prep(const float* __restrict__ Wl_z, const float* __restrict__ Wl_r,
                       const float* __restrict__ Wl_h, const float* __restrict__ W_lin) {
    int idx = blockIdx.x * blockDim.x + threadIdx.x;
    if (idx >= 7 * D * D) return;
    int m = idx / (D * D);
    int r = idx % (D * D);
    int k = r / D, n = r % D;
    float w;
    switch (m) {
        case 0: w = g_Wf[k * D + n]; break;
        case 1: w = Wl_z[(D + k) * D + n]; break;
        case 2: w = g_Wf[D * D + k * D + n]; break;
        case 3: w = Wl_r[(D + k) * D + n]; break;
        case 4: w = g_Wf[2 * D * D + k * D + n]; break;
        case 5: w = Wl_h[(D + k) * D + n]; break;
        default: w = W_lin[k * D + n]; break;
    }
    g_B[m * 16384 + k * D + n] = __float2half_rn(w);
}

// ---------------- main fused GRU kernel --------------------------------------
__device__ __forceinline__ void pfq(u32 smb, int buf, int mat, int q, int tid) {
    const char* src = (const char*)g_B + mat * 32768;
    u32 dst = smb + BUF0 + buf * 8704;
    #pragma unroll
    for (int it = 0; it < 2; ++it) {
        int e = tid + it * 256;       // 512 chunks: 32 rows x 16 chunks of 16B
        int r = e >> 4;
        int c = e & 15;
        const char* s = src + (q * 32 + r) * 256 + c * 16;
        u32 d = dst + r * PAB + c * 16;
        asm volatile("cp.async.cg.shared.global [%0], [%1], 16;" :: "r"(d), "l"(s));
    }
    asm volatile("cp.async.commit_group;");
}

__device__ __forceinline__ void gemm_q(const char* smem, int aoff, int boff,
                                       FragC acc[2][2], int wm, int wn, int q) {
    const __half* pah = (const __half*)(smem + aoff);
    const __half* pbh = (const __half*)(smem + boff);
    #pragma unroll
    for (int k0 = 0; k0 < 32; k0 += 16) {
        FragA ah[2];
        FragB bh[2];
        #pragma unroll
        for (int i = 0; i < 2; ++i) {
            wmma::load_matrix_sync(ah[i], pah + (wm * 32 + 16 * i) * PA + q * 32 + k0, PA);
            wmma::load_matrix_sync(bh[i], pbh + k0 * PA + wn * 32 + 16 * i, PA);
        }
        #pragma unroll
        for (int i = 0; i < 2; ++i)
            #pragma unroll
            for (int j = 0; j < 2; ++j)
                wmma::mma_sync(acc[i][j], ah[i], bh[j], acc[i][j]);
    }
}

// 3-buffer rotation, ONE barrier per k-quarter.
template <int NMAT>
__device__ __forceinline__ void run_stage(char* smem, u32 smb,
                                          int m0, int m1, int a0, int a1,
                                          FragC acc[2][2], int tid, int wm, int wn,
                                          bool pre_issued) {
    #pragma unroll
    for (int i = 0; i < 2; ++i)
        #pragma unroll
        for (int j = 0; j < 2; ++j) wmma::fill_fragment(acc[i][j], 0.0f);
    const int TQ = NMAT * 4;
    if (!pre_issued) pfq(smb, 0, m0, 0, tid);
    pfq(smb, 1, (TQ > 4 && 1 >= 4) ? m1 : m0, 1, tid);  // chunk 1 (always q=1 of m0)
    #pragma unroll 1
    for (int t = 0; t < TQ; ++t) {
        if (t + 1 < TQ) {
            asm volatile("cp.async.wait_group 1;");
        } else {
            asm volatile("cp.async.wait_group 0;");
        }
        __syncthreads();
        if (t + 2 < TQ)
            pfq(smb, (t + 2) % 3, ((t + 2) >> 2) ? m1 : m0, (t + 2) & 3, tid);
        gemm_q(smem, (t >> 2) ? a1 : a0, BUF0 + (t % 3) * 8704, acc, wm, wn, t & 3);
    }
    __syncthreads();   // all gemm reads done before SCR overlay writes
    float* scr = (float*)(smem + SCR);
    #pragma unroll
    for (int i = 0; i < 2; ++i)
        #pragma unroll
        for (int j = 0; j < 2; ++j)
            wmma::store_matrix_sync(scr + (wm * 32 + 16 * i) * 132 + wn * 32 + 16 * j,
                                    acc[i][j], 132, wmma::mem_row_major);
    __syncthreads();
}

__global__ void __launch_bounds__(256, 3)
k_main(const float* __restrict__ h, const float* __restrict__ b_lin,
       float* __restrict__ out) {
    extern __shared__ char smem[];
    u32 smb = s2u(smem);
    float* scr = (float*)(smem + SCR);
    float* sb = (float*)(smem + SB);
    int tid = threadIdx.x;
    int w = tid >> 5;
    int wm = w >> 2, wn = w & 3;     // 2 x 4 warp grid, 32x32 warp tiles
    int nb = blockIdx.x * ROWS;
    float* out_h = out + (long long)NN * D;

    // overlap first B prefetch with the prologue
    pfq(smb, 0, 0, 0, tid);

    // prologue: xa and h fp16 panels
    for (int idx = tid; idx < ROWS * 64; idx += 256) {
        int row = idx >> 6;
        int k = (idx & 63) * 2;
        int node = nb + row;
        float a0 = 0, a1 = 0, h0 = 0, h1 = 0;
        if (node < NN) {
            float2 va = *(const float2*)(g_agg + node * D + k);
            float dv = g_dinv[node];
            a0 = dv * va.x; a1 = dv * va.y;
            float2 vh = *(const float2*)(h + node * D + k);
            h0 = vh.x; h1 = vh.y;
        }
        int boff = (row * PA + k) * 2;
        *(u32*)(smem + XA_HI + boff) = pk2h(a0, a1);
        *(u32*)(smem + H_HI + boff) = pk2h(h0, h1);
    }
    for (int q = tid; q < 512; q += 256)
        sb[q] = (q < 384) ? g_bf[q] : b_lin[q - 384];
    __syncthreads();

    FragC acc[2][2];

    // ===== stage Z ===== (z staged fp16 into g_xs, dead after k_agg)
    run_stage<2>(smem, smb, 0, 1, XA_HI, H_HI, acc, tid, wm, wn, true);
    for (int e = tid; e < ROWS * 32; e += 256) {
        int r = e >> 5, c = (e & 31) * 4;
        int node = nb + r;
        if (node < NN) {
            float4 p = *(float4*)(scr + r * 132 + c);
            uint2 z;
            z.x = pk2h(sigm(p.x + sb[c]), sigm(p.y + sb[c + 1]));
            z.y = pk2h(sigm(p.z + sb[c + 2]), sigm(p.w + sb[c + 3]));
            *(uint2*)((u32*)g_xs + node * 64 + (c >> 1)) = z;
        }
    }
    __syncthreads();

    // ===== stage R =====
    run_stage<2>(smem, smb, 2, 3, XA_HI, H_HI, acc, tid, wm, wn, false);
    for (int e = tid; e < ROWS * 32; e += 256) {
        int r = e >> 5, c = (e & 31) * 4;
        int node = nb + r;
        float4 p = *(float4*)(scr + r * 132 + c);
        float4 hv = make_float4(0, 0, 0, 0);
        if (node < NN) hv = *(const float4*)(h + (long long)node * D + c);
        float r0 = hv.x * sigm(p.x + sb[D + c]);
        float r1 = hv.y * sigm(p.y + sb[D + c + 1]);
        float r2 = hv.z * sigm(p.z + sb[D + c + 2]);
        float r3 = hv.w * sigm(p.w + sb[D + c + 3]);
        int boff = (r * PA + c) * 2;
        *(u32*)(smem + H_HI + boff) = pk2h(r0, r1);
        *(u32*)(smem + H_HI + boff + 4) = pk2h(r2, r3);
    }
    __syncthreads();

    // ===== stage H =====
    run_stage<2>(smem, smb, 4, 5, XA_HI, H_HI, acc, tid, wm, wn, false);
    for (int e = tid; e < ROWS * 32; e += 256) {
        int r = e >> 5, c = (e & 31) * 4;
        int node = nb + r;
        float h0v[4] = {0, 0, 0, 0};
        if (node < NN) {
            float4 p = *(float4*)(scr + r * 132 + c);
            float4 hv = *(const float4*)(h + (long long)node * D + c);
            uint2 zq = *(const uint2*)((const u32*)g_xs + node * 64 + (c >> 1));
            float2 z01 = up2h(zq.x), z23 = up2h(zq.y);
            float pr[4] = {p.x, p.y, p.z, p.w};
            float hh[4] = {hv.x, hv.y, hv.z, hv.w};
            float zz[4] = {z01.x, z01.y, z23.x, z23.y};
            #pragma unroll
            for (int q = 0; q < 4; ++q) {
                float Ht = tanhf(pr[q] + sb[2 * D + c + q]);
                h0v[q] = zz[q] * hh[q] + (1.0f - zz[q]) * Ht;
            }
            *(float4*)(out_h + (long long)node * D + c) =
                make_float4(h0v[0], h0v[1], h0v[2], h0v[3]);
        }
        int boff = (r * PA + c) * 2;
        *(u32*)(smem + XA_HI + boff) = pk2h(fmaxf(h0v[0], 0.0f), fmaxf(h0v[1], 0.0f));
        *(u32*)(smem + XA_HI + boff + 4) = pk2h(fmaxf(h0v[2], 0.0f), fmaxf(h0v[3], 0.0f));
    }
    __syncthreads();

    // ===== stage L =====
    run_stage<1>(smem, smb, 6, 6, XA_HI, XA_HI, acc, tid, wm, wn, false);
    for (int e = tid; e < ROWS * 32; e += 256) {
        int r = e >> 5, c = (e & 31) * 4;
        int node = nb + r;
        if (node < NN) {
            float4 p = *(float4*)(scr + r * 132 + c);
            p.x += sb[3 * D + c];
            p.y += sb[3 * D + c + 1];
            p.z += sb[3 * D + c + 2];
            p.w += sb[3 * D + c + 3];
            *(float4*)(out + (long long)node * D + c) = p;
        }
    }
}

// ---------------- launch -----------------------------------------------------
extern "C" void kernel_launch(void* const* d_in, const int* in_sizes, int n_in,
                              void* d_out, int out_size) {
    const float* node_feat = (const float*)d_in[0];
    const int*   src       = (const int*)d_in[1];
    const int*   dst       = (const int*)d_in[2];
    const float* h         = (const float*)d_in[3];
    const float* Wc_z = (const float*)d_in[4];
    const float* bc_z = (const float*)d_in[5];
    const float* Wl_z = (const float*)d_in[6];
    const float* bl_z = (const float*)d_in[7];
    const float* Wc_r = (const float*)d_in[8];
    const float* bc_r = (const float*)d_in[9];
    const float* Wl_r = (const float*)d_in[10];
    const float* bl_r = (const float*)d_in[11];
    const float* Wc_h = (const float*)d_in[12];
    const float* bc_h = (const float*)d_in[13];
    const float* Wl_h = (const float*)d_in[14];
    const float* bl_h = (const float*)d_in[15];
    const float* W_lin = (const float*)d_in[16];
    const float* b_lin = (const float*)d_in[17];
    float* out = (float*)d_out;

    cudaFuncSetAttribute(k_main, cudaFuncAttributeMaxDynamicSharedMemorySize, SM_TOTAL);

    k_init<<<(NN + 255) / 256, 256>>>();
    k_count<<<(NE + 255) / 256, 256>>>(dst);
    k_prescale<<<(NN * 32 + 255) / 256, 256>>>(node_feat);
    k_scanA<<<NBLK, 256>>>();
    k_scanB<<<1, 256>>>();
    k_scanC<<<NBLK, 256>>>();
    k_scatter<<<(NE + 255) / 256, 256>>>(src, dst);
    k_agg<<<(NN + 7) / 8, 256>>>(node_feat);
    k_fuse<<<dim3(D, 3), D>>>(Wc_z, Wl_z, bc_z, bl_z,
                              Wc_r, Wl_r, bc_r, bl_r,
                              Wc_h, Wl_h, bc_h, bl_h);
    k_prep<<<(7 * D * D + 255) / 256, 256>>>(Wl_z, Wl_r, Wl_h, W_lin);
    k_main<<<(NN + ROWS - 1) / ROWS, 256, SM_TOTAL>>>(h, b_lin, out);
}

// round 15
// speedup vs baseline: 1.0385x; 1.0385x over previous
#include <cuda_runtime.h>
#include <cuda_fp16.h>
#include <mma.h>
#include <math.h>

#define NN 50000
#define NE 800000
#define D 128
#define ROWS 64           // rows per CTA tile
#define PA 136            // padded panel row (fp16 elems), 272B rows
#define PAB (PA * 2)
#define NBLK 196          // scan blocks: ceil(NN/256)

// smem byte offsets (per-CTA total 70656)
#define XA_HI 0           // 64 x 136 fp16 = 17408
#define H_HI  17408
#define BUF0  34816       // three 8704B B quarter-buffers (rotation)
#define SCR   34816       // f32 scratch 64x132 (33792B) overlays buffers
#define SB    68608       // 512 f32 biases
#define SM_TOTAL (68608 + 2048)

typedef unsigned int u32;
using namespace nvcuda;
typedef wmma::fragment<wmma::matrix_a, 16, 16, 16, __half, wmma::row_major> FragA;
typedef wmma::fragment<wmma::matrix_b, 16, 16, 16, __half, wmma::row_major> FragB;
typedef wmma::fragment<wmma::accumulator, 16, 16, 16, float> FragC;

// ---------------- scratch (device globals; no allocation allowed) ----------
__device__ int   g_cnt[NN];         // in-degree counts (excl self-loop)
__device__ int   g_part[NBLK];      // scan block partials
__device__ float g_dinv[NN];
__device__ __half g_xs[NN * D];     // fp16 pre-scaled features (gather source)
__device__ float g_agg[NN * D];     // f32 aggregate (written by k_agg)
__device__ int   g_rowptr[NN + 1];
__device__ int   g_cur[NN];
__device__ int   g_elist[NE];
__device__ float g_Wf[3 * D * D];
__device__ float g_bf[3 * D];
__device__ __half g_B[7 * 16384];   // 7 B mats [k][n] fp16

__device__ __forceinline__ u32 s2u(const void* p) {
    u32 a;
    asm("{ .reg .u64 t; cvta.to.shared.u64 t, %1; cvt.u32.u64 %0, t; }"
        : "=r"(a) : "l"(p));
    return a;
}
// MUFU-based fast sigmoid / tanh (rel err ~1e-6; exact saturation)
__device__ __forceinline__ float sigm(float x) {
    return __fdividef(1.0f, 1.0f + __expf(-x));
}
__device__ __forceinline__ float tanh_f(float x) {
    return 1.0f - __fdividef(2.0f, __expf(2.0f * x) + 1.0f);
}
__device__ __forceinline__ u32 pk2h(float x0, float x1) {
    __half2 hh = __floats2half2_rn(x0, x1);
    return *(u32*)&hh;
}
__device__ __forceinline__ float2 up2h(u32 v) {
    return __half22float2(*(__half2*)&v);
}

// ---------------- graph prep kernels ----------------------------------------
__global__ void k_init() {
    int i = blockIdx.x * blockDim.x + threadIdx.x;
    if (i < NN) g_cnt[i] = 0;
}
__global__ void k_count(const int* __restrict__ dst) {
    int e = blockIdx.x * blockDim.x + threadIdx.x;
    if (e < NE) atomicAdd(&g_cnt[dst[e]], 1);
}
// xs = fp16(dinv * x); dinv
__global__ void k_prescale(const float* __restrict__ x) {
    int idx = blockIdx.x * blockDim.x + threadIdx.x;
    if (idx >= NN * 32) return;
    int i = idx >> 5, c = idx & 31;
    float dv = rsqrtf((float)(g_cnt[i] + 1));
    float4 v = ((const float4*)x)[idx];
    uint2 q;
    q.x = pk2h(dv * v.x, dv * v.y);
    q.y = pk2h(dv * v.z, dv * v.w);
    ((uint2*)g_xs)[idx] = q;
    if (c == 0) g_dinv[i] = dv;
}
// ---- 3-phase exclusive scan of g_cnt -> g_rowptr ----
__global__ void k_scanA() {
    __shared__ int sh[256];
    int t = threadIdx.x;
    int idx = blockIdx.x * 256 + t;
    int v = (idx < NN) ? g_cnt[idx] : 0;
    sh[t] = v;
    __syncthreads();
    #pragma unroll
    for (int o = 1; o < 256; o <<= 1) {
        int u = (t >= o) ? sh[t - o] : 0;
        __syncthreads();
        sh[t] += u;
        __syncthreads();
    }
    if (idx < NN) g_rowptr[idx] = sh[t] - v;     // block-local exclusive
    if (t == 255) g_part[blockIdx.x] = sh[255];  // block total
}
__global__ void k_scanB() {
    __shared__ int sh[NBLK];
    int t = threadIdx.x;
    int v = (t < NBLK) ? g_part[t] : 0;
    if (t < NBLK) sh[t] = v;
    __syncthreads();
    for (int o = 1; o < NBLK; o <<= 1) {
        int u = (t >= o && t < NBLK) ? sh[t - o] : 0;
        __syncthreads();
        if (t < NBLK) sh[t] += u;
        __syncthreads();
    }
    if (t < NBLK) g_part[t] = sh[t] - v;         // exclusive
}
__global__ void k_scanC() {
    int idx = blockIdx.x * 256 + threadIdx.x;
    if (idx < NN) {
        int r = g_rowptr[idx] + g_part[blockIdx.x];
        g_rowptr[idx] = r;
        g_cur[idx] = r;
    }
    if (idx == 0) g_rowptr[NN] = NE;
}
// scatter edges into dst-grouped list (scalar atomics on 50K cursors)
__global__ void k_scatter(const int* __restrict__ src, const int* __restrict__ dst) {
    int e = blockIdx.x * blockDim.x + threadIdx.x;
    if (e >= NE) return;
    int pos = atomicAdd(&g_cur[dst[e]], 1);
    g_elist[pos] = src[e];
}
// warp-per-node aggregation: agg[n] = dinv[n]*x[n] + sum_{src in list} xs[src]
__global__ void k_agg(const float* __restrict__ x) {
    int n = blockIdx.x * 8 + (threadIdx.x >> 5);
    if (n >= NN) return;
    int lane = threadIdx.x & 31;
    float dv = g_dinv[n];
    float4 self = ((const float4*)x)[n * 32 + lane];
    float a0 = dv * self.x, a1 = dv * self.y, a2 = dv * self.z, a3 = dv * self.w;
    int j = g_rowptr[n], fin = g_rowptr[n + 1];
    for (; j + 1 < fin; j += 2) {
        int s0 = __ldg(&g_elist[j]);
        int s1 = __ldg(&g_elist[j + 1]);
        uint2 q0 = ((const uint2*)g_xs)[s0 * 32 + lane];
        uint2 q1 = ((const uint2*)g_xs)[s1 * 32 + lane];
        float2 p0 = up2h(q0.x), p1 = up2h(q0.y);
        float2 p2 = up2h(q1.x), p3 = up2h(q1.y);
        a0 += p0.x + p2.x; a1 += p0.y + p2.y;
        a2 += p1.x + p3.x; a3 += p1.y + p3.y;
    }
    if (j < fin) {
        int s0 = __ldg(&g_elist[j]);
        uint2 q0 = ((const uint2*)g_xs)[s0 * 32 + lane];
        float2 p0 = up2h(q0.x), p1 = up2h(q0.y);
        a0 += p0.x; a1 += p0.y; a2 += p1.x; a3 += p1.y;
    }
    ((float4*)g_agg)[n * 32 + lane] = make_float4(a0, a1, a2, a3);
}

// ---------------- weight fusion + fp16 quantization --------------------------
__global__ void k_fuse(const float* __restrict__ Wc_z, const float* __restrict__ Wl_z,
                       const float* __restrict__ bc_z, const float* __restrict__ bl_z,
                       const float* __restrict__ Wc_r, const float* __restrict__ Wl_r,
                       const float* __restrict__ bc_r, const float* __restrict__ bl_r,
                       const float* __restrict__ Wc_h, const float* __restrict__ Wl_h,
                       const float* __restrict__ bc_h, const float* __restrict__ bl_h) {
    int g = blockIdx.y;
    const float* Wc = (g == 0) ? Wc_z : (g == 1) ? Wc_r : Wc_h;
    const float* Wl = (g == 0) ? Wl_z : (g == 1) ? Wl_r : Wl_h;
    const float* bc = (g == 0) ? bc_z : (g == 1) ? bc_r : bc_h;
    const float* bl = (g == 0) ? bl_z : (g == 1) ? bl_r : bl_h;
    int i = blockIdx.x;
    int j = threadIdx.x;
    float s = 0.0f;
    #pragma unroll 8
    for (int k = 0; k < D; ++k) s += Wc[i * D + k] * Wl[k * D + j];
    g_Wf[g * D * D + i * D + j] = s;
    if (i == 0) {
        float b = bl[j];
        #pragma unroll 8
        for (int k = 0; k < D; ++k) b += bc[k] * Wl[k * D + j];
        g_bf[g * D + j] = b;
    }
}

__global__ void k_prep(const float* __restrict__ Wl_z, const float* __restrict__ Wl_r,
                       const float* __restrict__ Wl_h, const float* __restrict__ W_lin) {
    int idx = blockIdx.x * blockDim.x + threadIdx.x;
    if (idx >= 7 * D * D) return;
    int m = idx / (D * D);
    int r = idx % (D * D);
    int k = r / D, n = r % D;
    float w;
    switch (m) {
        case 0: w = g_Wf[k * D + n]; break;
        case 1: w = Wl_z[(D + k) * D + n]; break;
        case 2: w = g_Wf[D * D + k * D + n]; break;
        case 3: w = Wl_r[(D + k) * D + n]; break;
        case 4: w = g_Wf[2 * D * D + k * D + n]; break;
        case 5: w = Wl_h[(D + k) * D + n]; break;
        default: w = W_lin[k * D + n]; break;
    }
    g_B[m * 16384 + k * D + n] = __float2half_rn(w);
}

// ---------------- main fused GRU kernel --------------------------------------
__device__ __forceinline__ void pfq(u32 smb, int buf, int mat, int q, int tid) {
    const char* src = (const char*)g_B + mat * 32768;
    u32 dst = smb + BUF0 + buf * 8704;
    #pragma unroll
    for (int it = 0; it < 2; ++it) {
        int e = tid + it * 256;       // 512 chunks: 32 rows x 16 chunks of 16B
        int r = e >> 4;
        int c = e & 15;
        const char* s = src + (q * 32 + r) * 256 + c * 16;
        u32 d = dst + r * PAB + c * 16;
        asm volatile("cp.async.cg.shared.global [%0], [%1], 16;" :: "r"(d), "l"(s));
    }
    asm volatile("cp.async.commit_group;");
}

__device__ __forceinline__ void gemm_q(const char* smem, int aoff, int boff,
                                       FragC acc[2][2], int wm, int wn, int q) {
    const __half* pah = (const __half*)(smem + aoff);
    const __half* pbh = (const __half*)(smem + boff);
    #pragma unroll
    for (int k0 = 0; k0 < 32; k0 += 16) {
        FragA ah[2];
        FragB bh[2];
        #pragma unroll
        for (int i = 0; i < 2; ++i) {
            wmma::load_matrix_sync(ah[i], pah + (wm * 32 + 16 * i) * PA + q * 32 + k0, PA);
            wmma::load_matrix_sync(bh[i], pbh + k0 * PA + wn * 32 + 16 * i, PA);
        }
        #pragma unroll
        for (int i = 0; i < 2; ++i)
            #pragma unroll
            for (int j = 0; j < 2; ++j)
                wmma::mma_sync(acc[i][j], ah[i], bh[j], acc[i][j]);
    }
}

// 3-buffer rotation, ONE barrier per k-quarter.
template <int NMAT>
__device__ __forceinline__ void run_stage(char* smem, u32 smb,
                                          int m0, int m1, int a0, int a1,
                                          FragC acc[2][2], int tid, int wm, int wn,
                                          bool pre_issued) {
    #pragma unroll
    for (int i = 0; i < 2; ++i)
        #pragma unroll
        for (int j = 0; j < 2; ++j) wmma::fill_fragment(acc[i][j], 0.0f);
    const int TQ = NMAT * 4;
    if (!pre_issued) pfq(smb, 0, m0, 0, tid);
    pfq(smb, 1, m0, 1, tid);
    #pragma unroll 1
    for (int t = 0; t < TQ; ++t) {
        if (t + 1 < TQ) {
            asm volatile("cp.async.wait_group 1;");
        } else {
            asm volatile("cp.async.wait_group 0;");
        }
        __syncthreads();
        if (t + 2 < TQ)
            pfq(smb, (t + 2) % 3, ((t + 2) >> 2) ? m1 : m0, (t + 2) & 3, tid);
        gemm_q(smem, (t >> 2) ? a1 : a0, BUF0 + (t % 3) * 8704, acc, wm, wn, t & 3);
    }
    __syncthreads();   // all gemm reads done before SCR overlay writes
    float* scr = (float*)(smem + SCR);
    #pragma unroll
    for (int i = 0; i < 2; ++i)
        #pragma unroll
        for (int j = 0; j < 2; ++j)
            wmma::store_matrix_sync(scr + (wm * 32 + 16 * i) * 132 + wn * 32 + 16 * j,
                                    acc[i][j], 132, wmma::mem_row_major);
    __syncthreads();
}

__global__ void __launch_bounds__(256, 3)
k_main(const float* __restrict__ h, const float* __restrict__ b_lin,
       float* __restrict__ out) {
    extern __shared__ char smem[];
    u32 smb = s2u(smem);
    float* scr = (float*)(smem + SCR);
    float* sb = (float*)(smem + SB);
    int tid = threadIdx.x;
    int w = tid >> 5;
    int wm = w >> 2, wn = w & 3;     // 2 x 4 warp grid, 32x32 warp tiles
    int nb = blockIdx.x * ROWS;
    float* out_h = out + (long long)NN * D;

    // overlap first B prefetch with the prologue
    pfq(smb, 0, 0, 0, tid);

    // prologue: xa and h fp16 panels
    for (int idx = tid; idx < ROWS * 64; idx += 256) {
        int row = idx >> 6;
        int k = (idx & 63) * 2;
        int node = nb + row;
        float a0 = 0, a1 = 0, h0 = 0, h1 = 0;
        if (node < NN) {
            float2 va = *(const float2*)(g_agg + node * D + k);
            float dv = g_dinv[node];
            a0 = dv * va.x; a1 = dv * va.y;
            float2 vh = *(const float2*)(h + node * D + k);
            h0 = vh.x; h1 = vh.y;
        }
        int boff = (row * PA + k) * 2;
        *(u32*)(smem + XA_HI + boff) = pk2h(a0, a1);
        *(u32*)(smem + H_HI + boff) = pk2h(h0, h1);
    }
    for (int q = tid; q < 512; q += 256)
        sb[q] = (q < 384) ? g_bf[q] : b_lin[q - 384];
    __syncthreads();

    FragC acc[2][2];

    // ===== stage Z ===== (z staged f32 in out, rewritten at L)
    run_stage<2>(smem, smb, 0, 1, XA_HI, H_HI, acc, tid, wm, wn, true);
    for (int e = tid; e < ROWS * 32; e += 256) {
        int r = e >> 5, c = (e & 31) * 4;
        int node = nb + r;
        if (node < NN) {
            float4 p = *(float4*)(scr + r * 132 + c);
            float4 z = make_float4(sigm(p.x + sb[c]), sigm(p.y + sb[c + 1]),
                                   sigm(p.z + sb[c + 2]), sigm(p.w + sb[c + 3]));
            *(float4*)(out + (long long)node * D + c) = z;
        }
    }
    __syncthreads();

    // ===== stage R =====
    run_stage<2>(smem, smb, 2, 3, XA_HI, H_HI, acc, tid, wm, wn, false);
    for (int e = tid; e < ROWS * 32; e += 256) {
        int r = e >> 5, c = (e & 31) * 4;
        int node = nb + r;
        float4 p = *(float4*)(scr + r * 132 + c);
        float4 hv = make_float4(0, 0, 0, 0);
        if (node < NN) hv = *(const float4*)(h + (long long)node * D + c);
        float r0 = hv.x * sigm(p.x + sb[D + c]);
        float r1 = hv.y * sigm(p.y + sb[D + c + 1]);
        float r2 = hv.z * sigm(p.z + sb[D + c + 2]);
        float r3 = hv.w * sigm(p.w + sb[D + c + 3]);
        int boff = (r * PA + c) * 2;
        *(u32*)(smem + H_HI + boff) = pk2h(r0, r1);
        *(u32*)(smem + H_HI + boff + 4) = pk2h(r2, r3);
    }
    __syncthreads();

    // ===== stage H =====
    run_stage<2>(smem, smb, 4, 5, XA_HI, H_HI, acc, tid, wm, wn, false);
    for (int e = tid; e < ROWS * 32; e += 256) {
        int r = e >> 5, c = (e & 31) * 4;
        int node = nb + r;
        float h0v[4] = {0, 0, 0, 0};
        if (node < NN) {
            float4 p = *(float4*)(scr + r * 132 + c);
            float4 hv = *(const float4*)(h + (long long)node * D + c);
            float4 zv = *(const float4*)(out + (long long)node * D + c);
            float pr[4] = {p.x, p.y, p.z, p.w};
            float hh[4] = {hv.x, hv.y, hv.z, hv.w};
            float zz[4] = {zv.x, zv.y, zv.z, zv.w};
            #pragma unroll
            for (int q = 0; q < 4; ++q) {
                float Ht = tanh_f(pr[q] + sb[2 * D + c + q]);
                h0v[q] = zz[q] * hh[q] + (1.0f - zz[q]) * Ht;
            }
            *(float4*)(out_h + (long long)node * D + c) =
                make_float4(h0v[0], h0v[1], h0v[2], h0v[3]);
        }
        int boff = (r * PA + c) * 2;
        *(u32*)(smem + XA_HI + boff) = pk2h(fmaxf(h0v[0], 0.0f), fmaxf(h0v[1], 0.0f));
        *(u32*)(smem + XA_HI + boff + 4) = pk2h(fmaxf(h0v[2], 0.0f), fmaxf(h0v[3], 0.0f));
    }
    __syncthreads();

    // ===== stage L =====
    run_stage<1>(smem, smb, 6, 6, XA_HI, XA_HI, acc, tid, wm, wn, false);
    for (int e = tid; e < ROWS * 32; e += 256) {
        int r = e >> 5, c = (e & 31) * 4;
        int node = nb + r;
        if (node < NN) {
            float4 p = *(float4*)(scr + r * 132 + c);
            p.x += sb[3 * D + c];
            p.y += sb[3 * D + c + 1];
            p.z += sb[3 * D + c + 2];
            p.w += sb[3 * D + c + 3];
            *(float4*)(out + (long long)node * D + c) = p;
        }
    }
}

// ---------------- launch -----------------------------------------------------
extern "C" void kernel_launch(void* const* d_in, const int* in_sizes, int n_in,
                              void* d_out, int out_size) {
    const float* node_feat = (const float*)d_in[0];
    const int*   src       = (const int*)d_in[1];
    const int*   dst       = (const int*)d_in[2];
    const float* h         = (const float*)d_in[3];
    const float* Wc_z = (const float*)d_in[4];
    const float* bc_z = (const float*)d_in[5];
    const float* Wl_z = (const float*)d_in[6];
    const float* bl_z = (const float*)d_in[7];
    const float* Wc_r = (const float*)d_in[8];
    const float* bc_r = (const float*)d_in[9];
    const float* Wl_r = (const float*)d_in[10];
    const float* bl_r = (const float*)d_in[11];
    const float* Wc_h = (const float*)d_in[12];
    const float* bc_h = (const float*)d_in[13];
    const float* Wl_h = (const float*)d_in[14];
    const float* bl_h = (const float*)d_in[15];
    const float* W_lin = (const float*)d_in[16];
    const float* b_lin = (const float*)d_in[17];
    float* out = (float*)d_out;

    cudaFuncSetAttribute(k_main, cudaFuncAttributeMaxDynamicSharedMemorySize, SM_TOTAL);

    k_init<<<(NN + 255) / 256, 256>>>();
    k_count<<<(NE + 255) / 256, 256>>>(dst);
    k_prescale<<<(NN * 32 + 255) / 256, 256>>>(node_feat);
    k_scanA<<<NBLK, 256>>>();
    k_scanB<<<1, 256>>>();
    k_scanC<<<NBLK, 256>>>();
    k_scatter<<<(NE + 255) / 256, 256>>>(src, dst);
    k_agg<<<(NN + 7) / 8, 256>>>(node_feat);
    k_fuse<<<dim3(D, 3), D>>>(Wc_z, Wl_z, bc_z, bl_z,
                              Wc_r, Wl_r, bc_r, bl_r,
                              Wc_h, Wl_h, bc_h, bl_h);
    k_prep<<<(7 * D * D + 255) / 256, 256>>>(Wl_z, Wl_r, Wl_h, W_lin);
    k_main<<<(NN + ROWS - 1) / ROWS, 256, SM_TOTAL>>>(h, b_lin, out);
}